// round 16
// baseline (speedup 1.0000x reference)
#include <cuda_runtime.h>
#include <cstdint>

// Problem constants: B=8192, T=2048, H=5, input dim 1.
#define HID 5

typedef unsigned long long ull;

__device__ __forceinline__ float fast_tanh(float x) {
    float r;
    asm("tanh.approx.f32 %0, %1;" : "=f"(r) : "f"(x));
    return r;
}
__device__ __forceinline__ float fast_rcp(float x) {
    float r;
    asm("rcp.approx.f32 %0, %1;" : "=f"(r) : "f"(x));
    return r;
}
// Cell tanh via Pade(5,4) + RCP (rt 8 = half a MUFU.TANH) + clamp.
// tanh(x) ~ x(945+105y+y^2)/(945+420y+15y^2), y=x^2; |err| <= ~1.1e-3 near
// |x|~3.7, <2e-5 for |x|<=2; clamp handles saturation (err <= 6.7e-4).
__device__ __forceinline__ float cell_tanh(float x) {
    const float y = x * x;
    const float n = x * fmaf(y, fmaf(y, 1.0f, 105.0f), 945.0f);
    const float d = fmaf(y, fmaf(y, 15.0f, 420.0f), 945.0f);
    const float t = n * fast_rcp(d);
    return fminf(1.0f, fmaxf(-1.0f, t));
}
__device__ __forceinline__ ull pk2(float lo, float hi) {
    ull r;
    asm("mov.b64 %0, {%1, %2};" : "=l"(r) : "f"(lo), "f"(hi));
    return r;
}
__device__ __forceinline__ void upk2(ull v, float& lo, float& hi) {
    asm("mov.b64 {%0, %1}, %2;" : "=f"(lo), "=f"(hi) : "l"(v));
}
// Packed fp32x2 FMA (sm_100+): one instruction = 2 fp32 FMAs.
__device__ __forceinline__ ull fma2(ull a, ull b, ull c) {
    ull r;
    asm("fma.rn.f32x2 %0, %1, %2, %3;" : "=l"(r) : "l"(a), "l"(b), "l"(c));
    return r;
}

// ---------------- LSTM: mixed warp types, 2 warps/SMSP uniform -------------
// 8 warps/block on ALL S SMs -> every SMSP holds exactly 2 warps.
// A-type warp: 6 seqs x 5 lanes (lane = hidden unit), 4 tanh + 1 rcp /step.
// B-type warp: 8 seqs x 4 lanes (unit-ownership + shared unit 4), 5 tanh + 2 rcp.
// Binding SMSP = 4*16+8 + 5*16+16 = 168 cyc/step (was 192 with MUFU cell tanh).
// x is read DIRECTLY from the input layout [B,T]: each 8-step block is one
// 32B-aligned float4 pair per sequence = exact DRAM sectors, no pack pass.
__global__ void __launch_bounds__(256, 1) lstm_kernel(
    const float* __restrict__ x,      // [B,T]
    const float* __restrict__ W_ih,   // [20,1]
    const float* __restrict__ W_hh,   // [20,5]
    const float* __restrict__ b_ih,   // [20]
    const float* __restrict__ b_hh,   // [20]
    const float* __restrict__ W_fc,   // [1,5]
    const float* __restrict__ b_fc,   // [1]
    float* __restrict__ out,          // [B,1]
    int B, int T)
{
    const int lane = threadIdx.x & 31;
    const int w    = threadIdx.x >> 5;       // warp id in block, 0..7
    const int S    = gridDim.x;

    // Partition: each block has aB B-type warps (warps 0..aB-1) and 8-aB A-type.
    int nBtot = B - 48 * S;
    nBtot = (nBtot > 0) ? (nBtot + 1) / 2 : 0;
    const int qq = nBtot / S, rr = nBtot - qq * S;
    const int aB = qq + ((blockIdx.x < rr) ? 1 : 0);
    const int cumB = (blockIdx.x < rr) ? blockIdx.x * (qq + 1)
                                       : rr * (qq + 1) + (blockIdx.x - rr) * qq;
    const int bbase = 48 * blockIdx.x + 2 * cumB;  // first seq of this block

    const int nblk = T / 8;

    if (w < aB) {
        // ================= B-type: 8 seqs x 4 lanes =============
        const int q   = lane & 3;                  // lane role
        const int seqRaw = bbase + w * 8 + (lane >> 2);
        const bool valid = (seqRaw < B);
        const int s = valid ? seqRaw : (B - 1);

        ull wif, wgo, bif, bgo, whhif[HID], whhgo[HID];
        {
            const int ri = q, rf = 5 + q, rg = 10 + q, ro = 15 + q;
            wif = pk2(W_ih[ri] * 0.5f, W_ih[rf] * 0.5f);
            wgo = pk2(W_ih[rg],        W_ih[ro] * 0.5f);
            bif = pk2((b_ih[ri] + b_hh[ri]) * 0.5f, (b_ih[rf] + b_hh[rf]) * 0.5f);
            bgo = pk2((b_ih[rg] + b_hh[rg]),        (b_ih[ro] + b_hh[ro]) * 0.5f);
            #pragma unroll
            for (int k = 0; k < HID; k++) {
                whhif[k] = pk2(W_hh[ri * HID + k] * 0.5f, W_hh[rf * HID + k] * 0.5f);
                whhgo[k] = pk2(W_hh[rg * HID + k],        W_hh[ro * HID + k] * 0.5f);
            }
        }
        const int r4 = (q == 0) ? 4 : (q == 1) ? 14 : (q == 2) ? 9 : 19;
        const float s4 = (q == 1) ? 1.0f : 0.5f;
        const float a4 = s4;
        const float o4b = (q == 1) ? 0.0f : 0.5f;
        float w4 = W_ih[r4] * s4;
        float b4 = (b_ih[r4] + b_hh[r4]) * s4;
        float whh4[HID];
        #pragma unroll
        for (int k = 0; k < HID; k++) whh4[k] = W_hh[r4 * HID + k] * s4;

        const bool selHi = (q & 2) != 0;
        const bool selLo = (q & 1) != 0;

        float h[HID];
        #pragma unroll
        for (int j = 0; j < HID; j++) h[j] = 0.0f;
        float cq = 0.0f, c4 = 0.0f;

        const float4* xrow = reinterpret_cast<const float4*>(x + (size_t)s * T);
        float4 xu = xrow[0];
        float4 xv = xrow[1];

        for (int tb = 0; tb < nblk; tb++) {
            const int tn = (tb + 1 < nblk) ? (tb + 1) : tb;
            const float4 un = xrow[2 * tn + 0];
            const float4 vn = xrow[2 * tn + 1];
            const float xs[8] = {xu.x, xu.y, xu.z, xu.w, xv.x, xv.y, xv.z, xv.w};

            #pragma unroll
            for (int kk = 0; kk < 8; kk++) {
                const float xval = xs[kk];
                const ull x2 = pk2(xval, xval);

                ull zif = fma2(x2, wif, bif);
                ull zgo = fma2(x2, wgo, bgo);
                float z4 = fmaf(xval, w4, b4);
                #pragma unroll
                for (int k = 0; k < HID; k++) {
                    const ull h2 = pk2(h[k], h[k]);
                    zif = fma2(h2, whhif[k], zif);
                    zgo = fma2(h2, whhgo[k], zgo);
                    z4 = fmaf(h[k], whh4[k], z4);
                }

                float zi, zf, zg, zo;
                upk2(zif, zi, zf);
                upk2(zgo, zg, zo);

                const float ig = fmaf(0.5f, fast_tanh(zi), 0.5f);
                const float fg = fmaf(0.5f, fast_tanh(zf), 0.5f);
                const float gg = fast_tanh(zg);
                const float og = fmaf(0.5f, fast_tanh(zo), 0.5f);
                cq = fmaf(fg, cq, ig * gg);
                const float hq = og * cell_tanh(cq);

                const float v4 = fmaf(a4, fast_tanh(z4), o4b);
                const float rA = __shfl_xor_sync(0xffffffffu, v4, 1);
                const float p  = v4 * rA;
                const float px = __shfl_xor_sync(0xffffffffu, p, 2);
                const float P  = selHi ? px : p;
                const float rB = __shfl_xor_sync(0xffffffffu, v4, 2);
                const float rC = __shfl_xor_sync(0xffffffffu, rB, 1);
                const float F4 = selHi ? (selLo ? rA : v4) : (selLo ? rC : rB);
                const float O4 = selHi ? (selLo ? v4 : rA) : (selLo ? rB : rC);
                c4 = fmaf(F4, c4, P);
                const float h4 = O4 * cell_tanh(c4);

                h[0] = __shfl_sync(0xffffffffu, hq, 0, 4);
                h[1] = __shfl_sync(0xffffffffu, hq, 1, 4);
                h[2] = __shfl_sync(0xffffffffu, hq, 2, 4);
                h[3] = __shfl_sync(0xffffffffu, hq, 3, 4);
                h[4] = h4;
            }
            xu = un; xv = vn;
        }

        if (valid && q == 0) {
            float y = b_fc[0];
            #pragma unroll
            for (int j = 0; j < HID; j++) y = fmaf(fmaxf(h[j], 0.0f), W_fc[j], y);
            out[s] = y;
        }
    } else {
        // ================= A-type: 6 seqs x 5 lanes ============
        const int grp  = lane / 5;                 // 0..6
        const int role = lane - grp * 5;           // 0..4
        const int base = grp * 5;

        const int seqRaw = bbase + aB * 8 + (w - aB) * 6 + grp;
        const bool valid = (grp < 6) && (seqRaw < B);
        const int s = valid ? seqRaw : (B - 1);

        ull wif, wgo, bif, bgo, whhif[HID], whhgo[HID];
        {
            const int ri = role, rf = 5 + role, rg = 10 + role, ro = 15 + role;
            wif = pk2(W_ih[ri] * 0.5f, W_ih[rf] * 0.5f);
            wgo = pk2(W_ih[rg],        W_ih[ro] * 0.5f);
            bif = pk2((b_ih[ri] + b_hh[ri]) * 0.5f, (b_ih[rf] + b_hh[rf]) * 0.5f);
            bgo = pk2((b_ih[rg] + b_hh[rg]),        (b_ih[ro] + b_hh[ro]) * 0.5f);
            #pragma unroll
            for (int k = 0; k < HID; k++) {
                whhif[k] = pk2(W_hh[ri * HID + k] * 0.5f, W_hh[rf * HID + k] * 0.5f);
                whhgo[k] = pk2(W_hh[rg * HID + k],        W_hh[ro * HID + k] * 0.5f);
            }
        }

        float h[HID];
        #pragma unroll
        for (int j = 0; j < HID; j++) h[j] = 0.0f;
        float cq = 0.0f;

        const float4* xrow = reinterpret_cast<const float4*>(x + (size_t)s * T);
        float4 xu = xrow[0];
        float4 xv = xrow[1];

        for (int tb = 0; tb < nblk; tb++) {
            const int tn = (tb + 1 < nblk) ? (tb + 1) : tb;
            const float4 un = xrow[2 * tn + 0];
            const float4 vn = xrow[2 * tn + 1];
            const float xs[8] = {xu.x, xu.y, xu.z, xu.w, xv.x, xv.y, xv.z, xv.w};

            #pragma unroll
            for (int kk = 0; kk < 8; kk++) {
                const float xval = xs[kk];
                const ull x2 = pk2(xval, xval);

                ull zifA = fma2(x2, wif, bif);
                ull zgoA = fma2(x2, wgo, bgo);
                {
                    const ull h0 = pk2(h[0], h[0]);
                    const ull h1 = pk2(h[1], h[1]);
                    const ull h2 = pk2(h[2], h[2]);
                    zifA = fma2(h0, whhif[0], zifA);
                    zgoA = fma2(h0, whhgo[0], zgoA);
                    zifA = fma2(h1, whhif[1], zifA);
                    zgoA = fma2(h1, whhgo[1], zgoA);
                    zifA = fma2(h2, whhif[2], zifA);
                    zgoA = fma2(h2, whhgo[2], zgoA);
                }
                {
                    const ull h3 = pk2(h[3], h[3]);
                    const ull h4 = pk2(h[4], h[4]);
                    ull zifB = fma2(h3, whhif[3], pk2(0.0f, 0.0f));
                    ull zgoB = fma2(h3, whhgo[3], pk2(0.0f, 0.0f));
                    zifB = fma2(h4, whhif[4], zifB);
                    zgoB = fma2(h4, whhgo[4], zgoB);
                    const ull ONE2 = pk2(1.0f, 1.0f);
                    zifA = fma2(zifB, ONE2, zifA);
                    zgoA = fma2(zgoB, ONE2, zgoA);
                }

                float zi, zf, zg, zo;
                upk2(zifA, zi, zf);
                upk2(zgoA, zg, zo);

                const float ig = fmaf(0.5f, fast_tanh(zi), 0.5f);
                const float fg = fmaf(0.5f, fast_tanh(zf), 0.5f);
                const float gg = fast_tanh(zg);
                const float og = fmaf(0.5f, fast_tanh(zo), 0.5f);
                cq = fmaf(fg, cq, ig * gg);
                const float hq = og * cell_tanh(cq);

                h[0] = __shfl_sync(0xffffffffu, hq, base + 0);
                h[1] = __shfl_sync(0xffffffffu, hq, base + 1);
                h[2] = __shfl_sync(0xffffffffu, hq, base + 2);
                h[3] = __shfl_sync(0xffffffffu, hq, base + 3);
                h[4] = __shfl_sync(0xffffffffu, hq, base + 4);
            }
            xu = un; xv = vn;
        }

        if (valid && role == 0) {
            float y = b_fc[0];
            #pragma unroll
            for (int j = 0; j < HID; j++) y = fmaf(fmaxf(h[j], 0.0f), W_fc[j], y);
            out[s] = y;
        }
    }
}

extern "C" void kernel_launch(void* const* d_in, const int* in_sizes, int n_in,
                              void* d_out, int out_size) {
    const float* x    = (const float*)d_in[0];
    const float* W_ih = (const float*)d_in[1];
    const float* W_hh = (const float*)d_in[2];
    const float* b_ih = (const float*)d_in[3];
    const float* b_hh = (const float*)d_in[4];
    const float* W_fc = (const float*)d_in[5];
    const float* b_fc = (const float*)d_in[6];
    float* out = (float*)d_out;

    const int B = out_size;              // 8192
    const int T = in_sizes[0] / B;       // 2048

    // 8 warps/block on every SM -> exactly 2 warps per SMSP chip-wide.
    // B-type warps (8 seqs) absorb the seqs that 6-seq A-warps can't cover.
    int S = 0;
    cudaDeviceGetAttribute(&S, cudaDevAttrMultiProcessorCount, 0);
    if (S <= 0) S = 128;                 // defensive fallback
    lstm_kernel<<<S, 256>>>(x, W_ih, W_hh, b_ih, b_hh, W_fc, b_fc, out, B, T);
}

// round 17
// speedup vs baseline: 1.3110x; 1.3110x over previous
#include <cuda_runtime.h>
#include <cstdint>

// Problem constants: B=8192, T=2048, H=5, input dim 1.
#define HID 5

typedef unsigned long long ull;

__device__ __forceinline__ float fast_tanh(float x) {
    float r;
    asm("tanh.approx.f32 %0, %1;" : "=f"(r) : "f"(x));
    return r;
}
__device__ __forceinline__ ull pk2(float lo, float hi) {
    ull r;
    asm("mov.b64 %0, {%1, %2};" : "=l"(r) : "f"(lo), "f"(hi));
    return r;
}
__device__ __forceinline__ void upk2(ull v, float& lo, float& hi) {
    asm("mov.b64 {%0, %1}, %2;" : "=f"(lo), "=f"(hi) : "l"(v));
}
// Packed fp32x2 FMA (sm_100+): one instruction = 2 fp32 FMAs.
__device__ __forceinline__ ull fma2(ull a, ull b, ull c) {
    ull r;
    asm("fma.rn.f32x2 %0, %1, %2, %3;" : "=l"(r) : "l"(a), "l"(b), "l"(c));
    return r;
}

// ---------------- LSTM: mixed warp types, 2 warps/SMSP uniform -------------
// 8 warps/block on ALL S SMs -> every SMSP holds exactly 2 warps.
// A-type warp: 6 seqs x 5 lanes (lane = hidden unit), 5 tanh/warp-step.
// B-type warp: 8 seqs x 4 lanes (unit-ownership + shared unit 4), 7 tanh/step.
// Binding SMSP = (5+7)*16 = 192 cyc/step = measured wall (R15).
// All tanhs stay MUFU.TANH f32 (shortest chain latency; Pade+RCP regressed).
// x read DIRECTLY from [B,T]: each 8-step block = one 32B-aligned float4 pair
// per sequence = exact DRAM sectors, no pack pass (R16's good half).
__global__ void __launch_bounds__(256, 1) lstm_kernel(
    const float* __restrict__ x,      // [B,T]
    const float* __restrict__ W_ih,   // [20,1]
    const float* __restrict__ W_hh,   // [20,5]
    const float* __restrict__ b_ih,   // [20]
    const float* __restrict__ b_hh,   // [20]
    const float* __restrict__ W_fc,   // [1,5]
    const float* __restrict__ b_fc,   // [1]
    float* __restrict__ out,          // [B,1]
    int B, int T)
{
    const int lane = threadIdx.x & 31;
    const int w    = threadIdx.x >> 5;       // warp id in block, 0..7
    const int S    = gridDim.x;

    // Partition: each block has aB B-type warps (warps 0..aB-1) and 8-aB A-type.
    int nBtot = B - 48 * S;
    nBtot = (nBtot > 0) ? (nBtot + 1) / 2 : 0;
    const int qq = nBtot / S, rr = nBtot - qq * S;
    const int aB = qq + ((blockIdx.x < rr) ? 1 : 0);
    const int cumB = (blockIdx.x < rr) ? blockIdx.x * (qq + 1)
                                       : rr * (qq + 1) + (blockIdx.x - rr) * qq;
    const int bbase = 48 * blockIdx.x + 2 * cumB;  // first seq of this block

    const int nblk = T / 8;

    if (w < aB) {
        // ================= B-type: 8 seqs x 4 lanes =============
        const int q   = lane & 3;                  // lane role
        const int seqRaw = bbase + w * 8 + (lane >> 2);
        const bool valid = (seqRaw < B);
        const int s = valid ? seqRaw : (B - 1);

        ull wif, wgo, bif, bgo, whhif[HID], whhgo[HID];
        {
            const int ri = q, rf = 5 + q, rg = 10 + q, ro = 15 + q;
            wif = pk2(W_ih[ri] * 0.5f, W_ih[rf] * 0.5f);
            wgo = pk2(W_ih[rg],        W_ih[ro] * 0.5f);
            bif = pk2((b_ih[ri] + b_hh[ri]) * 0.5f, (b_ih[rf] + b_hh[rf]) * 0.5f);
            bgo = pk2((b_ih[rg] + b_hh[rg]),        (b_ih[ro] + b_hh[ro]) * 0.5f);
            #pragma unroll
            for (int k = 0; k < HID; k++) {
                whhif[k] = pk2(W_hh[ri * HID + k] * 0.5f, W_hh[rf * HID + k] * 0.5f);
                whhgo[k] = pk2(W_hh[rg * HID + k],        W_hh[ro * HID + k] * 0.5f);
            }
        }
        const int r4 = (q == 0) ? 4 : (q == 1) ? 14 : (q == 2) ? 9 : 19;
        const float s4 = (q == 1) ? 1.0f : 0.5f;
        const float a4 = s4;
        const float o4b = (q == 1) ? 0.0f : 0.5f;
        float w4 = W_ih[r4] * s4;
        float b4 = (b_ih[r4] + b_hh[r4]) * s4;
        float whh4[HID];
        #pragma unroll
        for (int k = 0; k < HID; k++) whh4[k] = W_hh[r4 * HID + k] * s4;

        const bool selHi = (q & 2) != 0;
        const bool selLo = (q & 1) != 0;

        float h[HID];
        #pragma unroll
        for (int j = 0; j < HID; j++) h[j] = 0.0f;
        float cq = 0.0f, c4 = 0.0f;

        const float4* xrow = reinterpret_cast<const float4*>(x + (size_t)s * T);
        float4 xu = xrow[0];
        float4 xv = xrow[1];

        for (int tb = 0; tb < nblk; tb++) {
            const int tn = (tb + 1 < nblk) ? (tb + 1) : tb;
            const float4 un = xrow[2 * tn + 0];
            const float4 vn = xrow[2 * tn + 1];
            const float xs[8] = {xu.x, xu.y, xu.z, xu.w, xv.x, xv.y, xv.z, xv.w};

            #pragma unroll
            for (int kk = 0; kk < 8; kk++) {
                const float xval = xs[kk];
                const ull x2 = pk2(xval, xval);

                ull zif = fma2(x2, wif, bif);
                ull zgo = fma2(x2, wgo, bgo);
                float z4 = fmaf(xval, w4, b4);
                #pragma unroll
                for (int k = 0; k < HID; k++) {
                    const ull h2 = pk2(h[k], h[k]);
                    zif = fma2(h2, whhif[k], zif);
                    zgo = fma2(h2, whhgo[k], zgo);
                    z4 = fmaf(h[k], whh4[k], z4);
                }

                float zi, zf, zg, zo;
                upk2(zif, zi, zf);
                upk2(zgo, zg, zo);

                const float ig = fmaf(0.5f, fast_tanh(zi), 0.5f);
                const float fg = fmaf(0.5f, fast_tanh(zf), 0.5f);
                const float gg = fast_tanh(zg);
                const float og = fmaf(0.5f, fast_tanh(zo), 0.5f);
                cq = fmaf(fg, cq, ig * gg);
                const float hq = og * fast_tanh(cq);

                const float v4 = fmaf(a4, fast_tanh(z4), o4b);
                const float rA = __shfl_xor_sync(0xffffffffu, v4, 1);
                const float p  = v4 * rA;
                const float px = __shfl_xor_sync(0xffffffffu, p, 2);
                const float P  = selHi ? px : p;
                const float rB = __shfl_xor_sync(0xffffffffu, v4, 2);
                const float rC = __shfl_xor_sync(0xffffffffu, rB, 1);
                const float F4 = selHi ? (selLo ? rA : v4) : (selLo ? rC : rB);
                const float O4 = selHi ? (selLo ? v4 : rA) : (selLo ? rB : rC);
                c4 = fmaf(F4, c4, P);
                const float h4 = O4 * fast_tanh(c4);

                h[0] = __shfl_sync(0xffffffffu, hq, 0, 4);
                h[1] = __shfl_sync(0xffffffffu, hq, 1, 4);
                h[2] = __shfl_sync(0xffffffffu, hq, 2, 4);
                h[3] = __shfl_sync(0xffffffffu, hq, 3, 4);
                h[4] = h4;
            }
            xu = un; xv = vn;
        }

        if (valid && q == 0) {
            float y = b_fc[0];
            #pragma unroll
            for (int j = 0; j < HID; j++) y = fmaf(fmaxf(h[j], 0.0f), W_fc[j], y);
            out[s] = y;
        }
    } else {
        // ================= A-type: 6 seqs x 5 lanes ============
        const int grp  = lane / 5;                 // 0..6
        const int role = lane - grp * 5;           // 0..4
        const int base = grp * 5;

        const int seqRaw = bbase + aB * 8 + (w - aB) * 6 + grp;
        const bool valid = (grp < 6) && (seqRaw < B);
        const int s = valid ? seqRaw : (B - 1);

        ull wif, wgo, bif, bgo, whhif[HID], whhgo[HID];
        {
            const int ri = role, rf = 5 + role, rg = 10 + role, ro = 15 + role;
            wif = pk2(W_ih[ri] * 0.5f, W_ih[rf] * 0.5f);
            wgo = pk2(W_ih[rg],        W_ih[ro] * 0.5f);
            bif = pk2((b_ih[ri] + b_hh[ri]) * 0.5f, (b_ih[rf] + b_hh[rf]) * 0.5f);
            bgo = pk2((b_ih[rg] + b_hh[rg]),        (b_ih[ro] + b_hh[ro]) * 0.5f);
            #pragma unroll
            for (int k = 0; k < HID; k++) {
                whhif[k] = pk2(W_hh[ri * HID + k] * 0.5f, W_hh[rf * HID + k] * 0.5f);
                whhgo[k] = pk2(W_hh[rg * HID + k],        W_hh[ro * HID + k] * 0.5f);
            }
        }

        float h[HID];
        #pragma unroll
        for (int j = 0; j < HID; j++) h[j] = 0.0f;
        float cq = 0.0f;

        const float4* xrow = reinterpret_cast<const float4*>(x + (size_t)s * T);
        float4 xu = xrow[0];
        float4 xv = xrow[1];

        for (int tb = 0; tb < nblk; tb++) {
            const int tn = (tb + 1 < nblk) ? (tb + 1) : tb;
            const float4 un = xrow[2 * tn + 0];
            const float4 vn = xrow[2 * tn + 1];
            const float xs[8] = {xu.x, xu.y, xu.z, xu.w, xv.x, xv.y, xv.z, xv.w};

            #pragma unroll
            for (int kk = 0; kk < 8; kk++) {
                const float xval = xs[kk];
                const ull x2 = pk2(xval, xval);

                ull zifA = fma2(x2, wif, bif);
                ull zgoA = fma2(x2, wgo, bgo);
                {
                    const ull h0 = pk2(h[0], h[0]);
                    const ull h1 = pk2(h[1], h[1]);
                    const ull h2 = pk2(h[2], h[2]);
                    zifA = fma2(h0, whhif[0], zifA);
                    zgoA = fma2(h0, whhgo[0], zgoA);
                    zifA = fma2(h1, whhif[1], zifA);
                    zgoA = fma2(h1, whhgo[1], zgoA);
                    zifA = fma2(h2, whhif[2], zifA);
                    zgoA = fma2(h2, whhgo[2], zgoA);
                }
                {
                    const ull h3 = pk2(h[3], h[3]);
                    const ull h4 = pk2(h[4], h[4]);
                    ull zifB = fma2(h3, whhif[3], pk2(0.0f, 0.0f));
                    ull zgoB = fma2(h3, whhgo[3], pk2(0.0f, 0.0f));
                    zifB = fma2(h4, whhif[4], zifB);
                    zgoB = fma2(h4, whhgo[4], zgoB);
                    const ull ONE2 = pk2(1.0f, 1.0f);
                    zifA = fma2(zifB, ONE2, zifA);
                    zgoA = fma2(zgoB, ONE2, zgoA);
                }

                float zi, zf, zg, zo;
                upk2(zifA, zi, zf);
                upk2(zgoA, zg, zo);

                const float ig = fmaf(0.5f, fast_tanh(zi), 0.5f);
                const float fg = fmaf(0.5f, fast_tanh(zf), 0.5f);
                const float gg = fast_tanh(zg);
                const float og = fmaf(0.5f, fast_tanh(zo), 0.5f);
                cq = fmaf(fg, cq, ig * gg);
                const float hq = og * fast_tanh(cq);

                h[0] = __shfl_sync(0xffffffffu, hq, base + 0);
                h[1] = __shfl_sync(0xffffffffu, hq, base + 1);
                h[2] = __shfl_sync(0xffffffffu, hq, base + 2);
                h[3] = __shfl_sync(0xffffffffu, hq, base + 3);
                h[4] = __shfl_sync(0xffffffffu, hq, base + 4);
            }
            xu = un; xv = vn;
        }

        if (valid && role == 0) {
            float y = b_fc[0];
            #pragma unroll
            for (int j = 0; j < HID; j++) y = fmaf(fmaxf(h[j], 0.0f), W_fc[j], y);
            out[s] = y;
        }
    }
}

extern "C" void kernel_launch(void* const* d_in, const int* in_sizes, int n_in,
                              void* d_out, int out_size) {
    const float* x    = (const float*)d_in[0];
    const float* W_ih = (const float*)d_in[1];
    const float* W_hh = (const float*)d_in[2];
    const float* b_ih = (const float*)d_in[3];
    const float* b_hh = (const float*)d_in[4];
    const float* W_fc = (const float*)d_in[5];
    const float* b_fc = (const float*)d_in[6];
    float* out = (float*)d_out;

    const int B = out_size;              // 8192
    const int T = in_sizes[0] / B;       // 2048

    // 8 warps/block on every SM -> exactly 2 warps per SMSP chip-wide.
    // B-type warps (8 seqs) absorb the seqs that 6-seq A-warps can't cover.
    int S = 0;
    cudaDeviceGetAttribute(&S, cudaDevAttrMultiProcessorCount, 0);
    if (S <= 0) S = 128;                 // defensive fallback
    lstm_kernel<<<S, 256>>>(x, W_ih, W_hh, b_ih, b_hh, W_fc, b_fc, out, B, T);
}